// round 2
// baseline (speedup 1.0000x reference)
#include <cuda_runtime.h>
#include <cuda_bf16.h>
#include <math.h>

// Problem constants (fixed by the dataset)
#define N_NODES   100000
#define N_EDGES   1600000
#define IN_F      256
#define OUT_F     256
#define D_LABEL   32
#define ALPHA     0.2f
#define EPS_RS    1e-9f

#define SCAN_BLK  512

// Scratch (device globals: allowed; no cudaMalloc anywhere)
__device__ float g_Wh[(size_t)N_NODES * OUT_F];   // ~100 MB
__device__ int   g_deg[N_NODES];
__device__ int   g_rowstart[N_NODES];
__device__ int   g_cursor[N_NODES];
__device__ int   g_edst[N_EDGES];
__device__ int   g_bsum[256];

// ---------------------------------------------------------------------------
// Kernel 0: zero degree array
// ---------------------------------------------------------------------------
__global__ void k_zero_deg(int n) {
    int i = blockIdx.x * blockDim.x + threadIdx.x;
    if (i < n) g_deg[i] = 0;
}

// ---------------------------------------------------------------------------
// Kernel 1: SGEMM  Wh = h @ W   (M x 256) @ (256 x 256), fp32
// BM=128, BN=128, BK=16, 256 threads, 8x8 microtile per thread
// ---------------------------------------------------------------------------
#define BM 128
#define BN 128
#define BK 16

__global__ __launch_bounds__(256, 2) void k_sgemm(
    const float* __restrict__ A,   // [M, 256]
    const float* __restrict__ B,   // [256, 256]
    int M)
{
    __shared__ float As[BK][BM];
    __shared__ float Bs[BK][BN];

    const int tid = threadIdx.x;
    const int tx  = tid & 15;      // 0..15
    const int ty  = tid >> 4;      // 0..15
    const int rowBase = blockIdx.y * BM;
    const int colBase = blockIdx.x * BN;

    float acc[8][8];
#pragma unroll
    for (int i = 0; i < 8; i++)
#pragma unroll
        for (int j = 0; j < 8; j++) acc[i][j] = 0.0f;

    for (int k0 = 0; k0 < IN_F; k0 += BK) {
        // Load A tile (128 x 16) -> transposed smem As[k][m]
#pragma unroll
        for (int t = 0; t < 2; t++) {
            int s  = tid * 2 + t;          // 0..511 float4 slots
            int r  = s >> 2;               // tile row 0..127
            int cv = s & 3;                // which float4 of the 16 cols
            int grow = rowBase + r;
            float4 v = make_float4(0.f, 0.f, 0.f, 0.f);
            if (grow < M)
                v = *(const float4*)(A + (size_t)grow * IN_F + k0 + cv * 4);
            As[cv * 4 + 0][r] = v.x;
            As[cv * 4 + 1][r] = v.y;
            As[cv * 4 + 2][r] = v.z;
            As[cv * 4 + 3][r] = v.w;
        }
        // Load B tile (16 x 128)
#pragma unroll
        for (int t = 0; t < 2; t++) {
            int s  = tid * 2 + t;          // 0..511
            int r  = s >> 5;               // 0..15
            int cv = s & 31;               // 0..31 float4s across 128 cols
            float4 v = *(const float4*)(B + (size_t)(k0 + r) * OUT_F + colBase + cv * 4);
            *(float4*)&Bs[r][cv * 4] = v;
        }
        __syncthreads();

#pragma unroll
        for (int k = 0; k < BK; k++) {
            float a[8], b[8];
#pragma unroll
            for (int i = 0; i < 8; i++) a[i] = As[k][ty * 8 + i];
#pragma unroll
            for (int j = 0; j < 8; j++) b[j] = Bs[k][tx * 8 + j];
#pragma unroll
            for (int i = 0; i < 8; i++)
#pragma unroll
                for (int j = 0; j < 8; j++)
                    acc[i][j] = fmaf(a[i], b[j], acc[i][j]);
        }
        __syncthreads();
    }

#pragma unroll
    for (int i = 0; i < 8; i++) {
        int grow = rowBase + ty * 8 + i;
        if (grow < M) {
            float* c = g_Wh + (size_t)grow * OUT_F + colBase + tx * 8;
            *(float4*)(c + 0) = make_float4(acc[i][0], acc[i][1], acc[i][2], acc[i][3]);
            *(float4*)(c + 4) = make_float4(acc[i][4], acc[i][5], acc[i][6], acc[i][7]);
        }
    }
}

// ---------------------------------------------------------------------------
// Kernel 2: degree histogram over src   (adj is INT32: [2, E] row-major)
// ---------------------------------------------------------------------------
__global__ void k_count(const int* __restrict__ adj, int E) {
    int e = blockIdx.x * blockDim.x + threadIdx.x;
    if (e < E) atomicAdd(&g_deg[adj[e]], 1);
}

// ---------------------------------------------------------------------------
// Kernels 3-5: exclusive scan of g_deg -> g_rowstart (and g_cursor copy)
// ---------------------------------------------------------------------------
__global__ void k_scan1(int n) {
    __shared__ int sm[SCAN_BLK];
    int i = blockIdx.x * SCAN_BLK + threadIdx.x;
    int v = (i < n) ? g_deg[i] : 0;
    sm[threadIdx.x] = v;
    __syncthreads();
    for (int off = 1; off < SCAN_BLK; off <<= 1) {
        int add = (threadIdx.x >= off) ? sm[threadIdx.x - off] : 0;
        __syncthreads();
        sm[threadIdx.x] += add;
        __syncthreads();
    }
    if (i < n) g_rowstart[i] = sm[threadIdx.x] - v;   // exclusive, block-local
    if (threadIdx.x == SCAN_BLK - 1) g_bsum[blockIdx.x] = sm[SCAN_BLK - 1];
}

__global__ void k_scan2(int nb) {
    __shared__ int sm[256];
    int t = threadIdx.x;
    int v = (t < nb) ? g_bsum[t] : 0;
    sm[t] = v;
    __syncthreads();
    for (int off = 1; off < 256; off <<= 1) {
        int add = (t >= off) ? sm[t - off] : 0;
        __syncthreads();
        sm[t] += add;
        __syncthreads();
    }
    if (t < nb) g_bsum[t] = sm[t] - v;                // exclusive block offsets
}

__global__ void k_scan3(int n) {
    int i = blockIdx.x * blockDim.x + threadIdx.x;
    if (i < n) {
        int rs = g_rowstart[i] + g_bsum[i >> 9];       // 512 = 1<<9
        g_rowstart[i] = rs;
        g_cursor[i]   = rs;
    }
}

// ---------------------------------------------------------------------------
// Kernel 6: scatter edges into CSR (dst per slot)
// ---------------------------------------------------------------------------
__global__ void k_scatter(const int* __restrict__ adj, int E) {
    int e = blockIdx.x * blockDim.x + threadIdx.x;
    if (e < E) {
        int s = adj[e];
        int d = adj[E + e];
        int p = atomicAdd(&g_cursor[s], 1);
        g_edst[p] = d;
    }
}

// ---------------------------------------------------------------------------
// Kernel 7: warp-per-node attention + aggregation
// ---------------------------------------------------------------------------
#define MAXD 96

__device__ __forceinline__ float warp_sum32(float v) {
    v += __shfl_xor_sync(0xffffffffu, v, 16);
    v += __shfl_xor_sync(0xffffffffu, v, 8);
    v += __shfl_xor_sync(0xffffffffu, v, 4);
    v += __shfl_xor_sync(0xffffffffu, v, 2);
    v += __shfl_xor_sync(0xffffffffu, v, 1);
    return v;
}

__global__ __launch_bounds__(256) void k_aggregate(
    const float* __restrict__ label,   // [N, 32]
    float* __restrict__ out,           // [N, 256]
    int n)
{
    __shared__ float sE[8][MAXD];
    __shared__ int   sJ[8][MAXD];

    const int wl   = threadIdx.x >> 5;             // warp in block
    const int lane = threadIdx.x & 31;
    const int w    = blockIdx.x * 8 + wl;          // node id
    if (w >= n) return;

    const float labi = label[(size_t)w * D_LABEL + lane];
    const int start = g_rowstart[w];
    const int d     = g_deg[w];

    // Pass 1: attention logits -> exp, denominator; cache in smem
    float denom = 0.0f;
    for (int k = 0; k < d; k++) {
        int j = g_edst[start + k];
        float v = labi * label[(size_t)j * D_LABEL + lane];
        v = warp_sum32(v);
        float e = (v >= 0.0f) ? v : ALPHA * v;
        float ex = expf(e);
        denom += ex;
        if (k < MAXD && lane == 0) { sE[wl][k] = ex; sJ[wl][k] = j; }
    }
    const float inv = 1.0f / fmaxf(denom, EPS_RS);
    __syncwarp();

    // Pass 2: weighted accumulation of Wh rows
    float acc[8];
#pragma unroll
    for (int q = 0; q < 8; q++) acc[q] = 0.0f;

    for (int k = 0; k < d; k++) {
        float ex; int j;
        if (k < MAXD) {
            ex = sE[wl][k];
            j  = sJ[wl][k];
        } else {
            j = g_edst[start + k];
            float v = labi * label[(size_t)j * D_LABEL + lane];
            v = warp_sum32(v);
            float e = (v >= 0.0f) ? v : ALPHA * v;
            ex = expf(e);
        }
        float wt = ex * inv;
        const float* wh = g_Wh + (size_t)j * OUT_F + lane;
#pragma unroll
        for (int q = 0; q < 8; q++)
            acc[q] = fmaf(wt, wh[q * 32], acc[q]);
    }

#pragma unroll
    for (int q = 0; q < 8; q++)
        out[(size_t)w * OUT_F + q * 32 + lane] = acc[q];
}

// ---------------------------------------------------------------------------
// Launch
// ---------------------------------------------------------------------------
extern "C" void kernel_launch(void* const* d_in, const int* in_sizes, int n_in,
                              void* d_out, int out_size)
{
    const float* h     = (const float*)d_in[0];   // [N, 256] fp32
    const float* label = (const float*)d_in[1];   // [N, 32]  fp32
    const float* W     = (const float*)d_in[2];   // [256, 256] fp32
    const int*   adj   = (const int*)d_in[3];     // [2, E] int32 (JAX x64 disabled)
    float*       out   = (float*)d_out;

    const int N = in_sizes[0] / IN_F;      // 100000
    const int E = in_sizes[3] / 2;         // 1600000

    const int T = 256;
    const int gbN = (N + T - 1) / T;
    const int gbE = (E + T - 1) / T;

    k_zero_deg<<<gbN, T>>>(N);

    dim3 ggrid((OUT_F + BN - 1) / BN, (N + BM - 1) / BM);
    k_sgemm<<<ggrid, 256>>>(h, W, N);

    k_count<<<gbE, T>>>(adj, E);

    int nb = (N + SCAN_BLK - 1) / SCAN_BLK;
    k_scan1<<<nb, SCAN_BLK>>>(N);
    k_scan2<<<1, 256>>>(nb);
    k_scan3<<<gbN, T>>>(N);

    k_scatter<<<gbE, T>>>(adj, E);

    k_aggregate<<<(N + 7) / 8, 256>>>(label, out, N);
}

// round 4
// speedup vs baseline: 1.2946x; 1.2946x over previous
#include <cuda_runtime.h>
#include <cuda_bf16.h>
#include <math.h>
#include <stdint.h>

// Problem constants (fixed by the dataset)
#define N_NODES   100000
#define N_EDGES   1600000
#define IN_F      256
#define OUT_F     256
#define D_LABEL   32
#define ALPHA     0.2f
#define EPS_RS    1e-9f

#define SCAN_BLK  512

// Scratch (device globals: allowed; no cudaMalloc anywhere)
__device__ float g_Wh[(size_t)N_NODES * OUT_F];   // ~100 MB
__device__ int   g_deg[N_NODES];
__device__ int   g_rowstart[N_NODES];
__device__ int   g_cursor[N_NODES];
__device__ int   g_edst[N_EDGES];
__device__ int   g_bsum[256];
// W transposed + bf16 split: Wt[n][k] = W[k][n]
__device__ __nv_bfloat16 g_Wt_hi[256 * 256];
__device__ __nv_bfloat16 g_Wt_lo[256 * 256];

// ---------------------------------------------------------------------------
// helpers
// ---------------------------------------------------------------------------
__device__ __forceinline__ uint32_t smem_u32(const void* p) {
    uint32_t a;
    asm("{ .reg .u64 t; cvta.to.shared.u64 t, %1; cvt.u32.u64 %0, t; }"
        : "=r"(a) : "l"(p));
    return a;
}

__device__ __forceinline__ void ldsm_x4(uint32_t* r, uint32_t addr) {
    asm volatile("ldmatrix.sync.aligned.m8n8.x4.shared.b16 {%0,%1,%2,%3}, [%4];"
                 : "=r"(r[0]), "=r"(r[1]), "=r"(r[2]), "=r"(r[3]) : "r"(addr));
}
__device__ __forceinline__ void ldsm_x2(uint32_t* r, uint32_t addr) {
    asm volatile("ldmatrix.sync.aligned.m8n8.x2.shared.b16 {%0,%1}, [%2];"
                 : "=r"(r[0]), "=r"(r[1]) : "r"(addr));
}
__device__ __forceinline__ void mma_bf16(float* c, const uint32_t* a, const uint32_t* b) {
    asm volatile(
        "mma.sync.aligned.m16n8k16.row.col.f32.bf16.bf16.f32 "
        "{%0,%1,%2,%3}, {%4,%5,%6,%7}, {%8,%9}, {%0,%1,%2,%3};"
        : "+f"(c[0]), "+f"(c[1]), "+f"(c[2]), "+f"(c[3])
        : "r"(a[0]), "r"(a[1]), "r"(a[2]), "r"(a[3]), "r"(b[0]), "r"(b[1]));
}

// ---------------------------------------------------------------------------
// Kernel 0: zero degree array
// ---------------------------------------------------------------------------
__global__ void k_zero_deg(int n) {
    int i = blockIdx.x * blockDim.x + threadIdx.x;
    if (i < n) g_deg[i] = 0;
}

// ---------------------------------------------------------------------------
// Kernel P: W [K,N] fp32 -> Wt_hi/Wt_lo [N,K] bf16 split
// ---------------------------------------------------------------------------
__global__ void k_prep_W(const float* __restrict__ W) {
    int i = blockIdx.x * 256 + threadIdx.x;     // 0..65535
    int n = i >> 8, k = i & 255;
    float w = W[k * 256 + n];
    __nv_bfloat16 hi = __float2bfloat16(w);
    __nv_bfloat16 lo = __float2bfloat16(w - __bfloat162float(hi));
    g_Wt_hi[n * 256 + k] = hi;
    g_Wt_lo[n * 256 + k] = lo;
}

// ---------------------------------------------------------------------------
// Kernel 1: HMMA GEMM  Wh = h @ W  via bf16 hi/lo split (3 products)
// CTA: 128 M x 128 N, grid (2 N-halves, M/128). 256 thr, warps 2x4, 64x32/warp.
// B both halves full-K resident in smem (rows padded 528B).
// A fp32 reg-prefetched per K-chunk(32), converted to hi/lo, double-buffered.
// ---------------------------------------------------------------------------
#define B_ROW 528
#define A_ROW 80
#define SM_BH 0
#define SM_BL 67584
#define SM_A0 135168
#define A_STAGE 20480
#define SM_AL_OFF 10240
#define GSM_TOTAL 176128

__global__ __launch_bounds__(256, 1) void k_gemm_mma(const float* __restrict__ A, int M)
{
    extern __shared__ __align__(16) char sm[];
    const uint32_t sbase = smem_u32(sm);
    const int tid  = threadIdx.x;
    const int lane = tid & 31;
    const int wid  = tid >> 5;
    const int wm   = wid >> 2;          // 0..1
    const int wn   = wid & 3;           // 0..3
    const int rowBase = blockIdx.y * 128;
    const int colBase = blockIdx.x * 128;

    // ---- stage B (hi+lo, full K) into smem
    {
        const char* srcH = (const char*)(g_Wt_hi + (size_t)colBase * 256);
        const char* srcL = (const char*)(g_Wt_lo + (size_t)colBase * 256);
        for (int i = tid; i < 128 * 32; i += 256) {
            int n = i >> 5, c = i & 31;
            *(uint4*)(sm + SM_BH + n * B_ROW + c * 16) =
                *(const uint4*)(srcH + n * 512 + c * 16);
            *(uint4*)(sm + SM_BL + n * B_ROW + c * 16) =
                *(const uint4*)(srcL + n * 512 + c * 16);
        }
    }

    float acc[4][4][4];
#pragma unroll
    for (int i = 0; i < 4; i++)
#pragma unroll
        for (int j = 0; j < 4; j++)
#pragma unroll
            for (int q = 0; q < 4; q++) acc[i][j][q] = 0.0f;

    // A prefetch: thread -> (row, k-half of 16 floats)
    const int ar   = tid >> 1;
    const int ahlf = tid & 1;
    const int grow = rowBase + ar;
    const float* aptr = A + (size_t)grow * IN_F + ahlf * 16;

    float4 pf[4];
#pragma unroll
    for (int q = 0; q < 4; q++) pf[q] = make_float4(0.f, 0.f, 0.f, 0.f);
    if (grow < M) {
#pragma unroll
        for (int q = 0; q < 4; q++) pf[q] = *(const float4*)(aptr + q * 4);
    }

    // fragment address bases
    const uint32_t a_frag_off = (uint32_t)((wm * 64 + (lane & 15)) * A_ROW + (lane >> 4) * 16);
    const int bl_ = lane & 15;
    const uint32_t b_frag_off = (uint32_t)((wn * 32 + (bl_ & 7)) * B_ROW + ((bl_ >> 3) & 1) * 16);
    const uint32_t sts_off = (uint32_t)(ar * A_ROW + ahlf * 32);

    for (int c = 0; c < 8; c++) {
        const int stage = c & 1;
        // convert pf (16 f32) -> bf16 hi/lo, store to smem stage
        {
            uint32_t hv[8], lv[8];
#pragma unroll
            for (int q = 0; q < 4; q++) {
                float x[4] = { pf[q].x, pf[q].y, pf[q].z, pf[q].w };
#pragma unroll
                for (int e = 0; e < 2; e++) {
                    float f0 = x[e * 2], f1 = x[e * 2 + 1];
                    __nv_bfloat16 h0 = __float2bfloat16(f0);
                    __nv_bfloat16 h1 = __float2bfloat16(f1);
                    __nv_bfloat16 l0 = __float2bfloat16(f0 - __bfloat162float(h0));
                    __nv_bfloat16 l1 = __float2bfloat16(f1 - __bfloat162float(h1));
                    hv[q * 2 + e] = (uint32_t)__bfloat16_as_ushort(h0) |
                                    ((uint32_t)__bfloat16_as_ushort(h1) << 16);
                    lv[q * 2 + e] = (uint32_t)__bfloat16_as_ushort(l0) |
                                    ((uint32_t)__bfloat16_as_ushort(l1) << 16);
                }
            }
            char* ab = sm + SM_A0 + stage * A_STAGE + sts_off;
            *(uint4*)(ab +  0) = make_uint4(hv[0], hv[1], hv[2], hv[3]);
            *(uint4*)(ab + 16) = make_uint4(hv[4], hv[5], hv[6], hv[7]);
            *(uint4*)(ab + SM_AL_OFF +  0) = make_uint4(lv[0], lv[1], lv[2], lv[3]);
            *(uint4*)(ab + SM_AL_OFF + 16) = make_uint4(lv[4], lv[5], lv[6], lv[7]);
        }
        __syncthreads();

        // prefetch next chunk (overlaps with compute below)
        if (c < 7 && grow < M) {
#pragma unroll
            for (int q = 0; q < 4; q++)
                pf[q] = *(const float4*)(aptr + (c + 1) * 32 + q * 4);
        }

        // compute this chunk
        const uint32_t aB = sbase + SM_A0 + stage * A_STAGE + a_frag_off;
        const uint32_t bB = sbase + b_frag_off + c * 64;   // k0 bytes = c*32*2
#pragma unroll
        for (int ks = 0; ks < 2; ks++) {
            uint32_t ahf[4][4], alf[4][4];
#pragma unroll
            for (int mf = 0; mf < 4; mf++) {
                ldsm_x4(ahf[mf], aB + mf * (16 * A_ROW) + ks * 32);
                ldsm_x4(alf[mf], aB + SM_AL_OFF + mf * (16 * A_ROW) + ks * 32);
            }
            uint32_t bhf[4][2], blf[4][2];
#pragma unroll
            for (int nf = 0; nf < 4; nf++) {
                ldsm_x2(bhf[nf], bB + SM_BH + nf * (8 * B_ROW) + ks * 32);
                ldsm_x2(blf[nf], bB + SM_BL + nf * (8 * B_ROW) + ks * 32);
            }
#pragma unroll
            for (int mf = 0; mf < 4; mf++)
#pragma unroll
                for (int nf = 0; nf < 4; nf++) {
                    mma_bf16(acc[mf][nf], ahf[mf], bhf[nf]);
                    mma_bf16(acc[mf][nf], ahf[mf], blf[nf]);
                    mma_bf16(acc[mf][nf], alf[mf], bhf[nf]);
                }
        }
    }

    // epilogue
#pragma unroll
    for (int mf = 0; mf < 4; mf++) {
        int r0 = rowBase + wm * 64 + mf * 16 + (lane >> 2);
#pragma unroll
        for (int nf = 0; nf < 4; nf++) {
            int col = colBase + wn * 32 + nf * 8 + 2 * (lane & 3);
            if (r0 < M)
                *(float2*)(g_Wh + (size_t)r0 * OUT_F + col) =
                    make_float2(acc[mf][nf][0], acc[mf][nf][1]);
            if (r0 + 8 < M)
                *(float2*)(g_Wh + (size_t)(r0 + 8) * OUT_F + col) =
                    make_float2(acc[mf][nf][2], acc[mf][nf][3]);
        }
    }
}

// ---------------------------------------------------------------------------
// Kernel 2: degree histogram over src   (adj is INT32: [2, E] row-major)
// ---------------------------------------------------------------------------
__global__ void k_count(const int* __restrict__ adj, int E) {
    int e = blockIdx.x * blockDim.x + threadIdx.x;
    if (e < E) atomicAdd(&g_deg[adj[e]], 1);
}

// ---------------------------------------------------------------------------
// Kernels 3-5: exclusive scan of g_deg -> g_rowstart (and g_cursor copy)
// ---------------------------------------------------------------------------
__global__ void k_scan1(int n) {
    __shared__ int sm[SCAN_BLK];
    int i = blockIdx.x * SCAN_BLK + threadIdx.x;
    int v = (i < n) ? g_deg[i] : 0;
    sm[threadIdx.x] = v;
    __syncthreads();
    for (int off = 1; off < SCAN_BLK; off <<= 1) {
        int add = (threadIdx.x >= off) ? sm[threadIdx.x - off] : 0;
        __syncthreads();
        sm[threadIdx.x] += add;
        __syncthreads();
    }
    if (i < n) g_rowstart[i] = sm[threadIdx.x] - v;
    if (threadIdx.x == SCAN_BLK - 1) g_bsum[blockIdx.x] = sm[SCAN_BLK - 1];
}

__global__ void k_scan2(int nb) {
    __shared__ int sm[256];
    int t = threadIdx.x;
    int v = (t < nb) ? g_bsum[t] : 0;
    sm[t] = v;
    __syncthreads();
    for (int off = 1; off < 256; off <<= 1) {
        int add = (t >= off) ? sm[t - off] : 0;
        __syncthreads();
        sm[t] += add;
        __syncthreads();
    }
    if (t < nb) g_bsum[t] = sm[t] - v;
}

__global__ void k_scan3(int n) {
    int i = blockIdx.x * blockDim.x + threadIdx.x;
    if (i < n) {
        int rs = g_rowstart[i] + g_bsum[i >> 9];
        g_rowstart[i] = rs;
        g_cursor[i]   = rs;
    }
}

// ---------------------------------------------------------------------------
// Kernel 6: scatter edges into CSR (dst per slot)
// ---------------------------------------------------------------------------
__global__ void k_scatter(const int* __restrict__ adj, int E) {
    int e = blockIdx.x * blockDim.x + threadIdx.x;
    if (e < E) {
        int s = adj[e];
        int d = adj[E + e];
        int p = atomicAdd(&g_cursor[s], 1);
        g_edst[p] = d;
    }
}

// ---------------------------------------------------------------------------
// Kernel 7: warp-per-node attention + aggregation
// ---------------------------------------------------------------------------
#define MAXD 96

__device__ __forceinline__ float warp_sum32(float v) {
    v += __shfl_xor_sync(0xffffffffu, v, 16);
    v += __shfl_xor_sync(0xffffffffu, v, 8);
    v += __shfl_xor_sync(0xffffffffu, v, 4);
    v += __shfl_xor_sync(0xffffffffu, v, 2);
    v += __shfl_xor_sync(0xffffffffu, v, 1);
    return v;
}

__global__ __launch_bounds__(256) void k_aggregate(
    const float* __restrict__ label,   // [N, 32]
    float* __restrict__ out,           // [N, 256]
    int n)
{
    __shared__ float sE[8][MAXD];
    __shared__ int   sJ[8][MAXD];

    const int wl   = threadIdx.x >> 5;
    const int lane = threadIdx.x & 31;
    const int w    = blockIdx.x * 8 + wl;
    if (w >= n) return;

    const float labi = label[(size_t)w * D_LABEL + lane];
    const int start = g_rowstart[w];
    const int d     = g_deg[w];

    float denom = 0.0f;
    for (int k = 0; k < d; k++) {
        int j = g_edst[start + k];
        float v = labi * label[(size_t)j * D_LABEL + lane];
        v = warp_sum32(v);
        float e = (v >= 0.0f) ? v : ALPHA * v;
        float ex = expf(e);
        denom += ex;
        if (k < MAXD && lane == 0) { sE[wl][k] = ex; sJ[wl][k] = j; }
    }
    const float inv = 1.0f / fmaxf(denom, EPS_RS);
    __syncwarp();

    float acc[8];
#pragma unroll
    for (int q = 0; q < 8; q++) acc[q] = 0.0f;

    for (int k = 0; k < d; k++) {
        float ex; int j;
        if (k < MAXD) {
            ex = sE[wl][k];
            j  = sJ[wl][k];
        } else {
            j = g_edst[start + k];
            float v = labi * label[(size_t)j * D_LABEL + lane];
            v = warp_sum32(v);
            float e = (v >= 0.0f) ? v : ALPHA * v;
            ex = expf(e);
        }
        float wt = ex * inv;
        const float* wh = g_Wh + (size_t)j * OUT_F + lane;
#pragma unroll
        for (int q = 0; q < 8; q++)
            acc[q] = fmaf(wt, wh[q * 32], acc[q]);
    }

#pragma unroll
    for (int q = 0; q < 8; q++)
        out[(size_t)w * OUT_F + q * 32 + lane] = acc[q];
}

// ---------------------------------------------------------------------------
// Launch
// ---------------------------------------------------------------------------
extern "C" void kernel_launch(void* const* d_in, const int* in_sizes, int n_in,
                              void* d_out, int out_size)
{
    const float* h     = (const float*)d_in[0];   // [N, 256] fp32
    const float* label = (const float*)d_in[1];   // [N, 32]  fp32
    const float* W     = (const float*)d_in[2];   // [256, 256] fp32
    const int*   adj   = (const int*)d_in[3];     // [2, E] int32
    float*       out   = (float*)d_out;

    const int N = in_sizes[0] / IN_F;      // 100000
    const int E = in_sizes[3] / 2;         // 1600000

    const int T = 256;
    const int gbN = (N + T - 1) / T;
    const int gbE = (E + T - 1) / T;

    static bool attr_done = false;
    if (!attr_done) {
        cudaFuncSetAttribute(k_gemm_mma, cudaFuncAttributeMaxDynamicSharedMemorySize, GSM_TOTAL);
        attr_done = true;
    }

    k_zero_deg<<<gbN, T>>>(N);            // launch 0
    k_prep_W<<<256, 256>>>(W);            // launch 1
    k_count<<<gbE, T>>>(adj, E);          // launch 2

    dim3 ggrid(2, (N + 127) / 128);
    k_gemm_mma<<<ggrid, 256, GSM_TOTAL>>>(h, N);   // launch 3 (ncu lands here)

    int nb = (N + SCAN_BLK - 1) / SCAN_BLK;
    k_scan1<<<nb, SCAN_BLK>>>(N);
    k_scan2<<<1, 256>>>(nb);
    k_scan3<<<gbN, T>>>(N);
    k_scatter<<<gbE, T>>>(adj, E);

    k_aggregate<<<(N + 7) / 8, 256>>>(label, out, N);
}

// round 5
// speedup vs baseline: 1.4462x; 1.1171x over previous
#include <cuda_runtime.h>
#include <cuda_bf16.h>
#include <math.h>
#include <stdint.h>

// Problem constants (fixed by the dataset)
#define N_NODES   100000
#define N_EDGES   1600000
#define IN_F      256
#define OUT_F     256
#define D_LABEL   32
#define ALPHA     0.2f
#define EPS_RS    1e-9f

#define SCAN_BLK  512

// Scratch (device globals: allowed; no cudaMalloc anywhere)
__device__ float g_Wh[(size_t)N_NODES * OUT_F];   // ~100 MB
__device__ int   g_deg[N_NODES];
__device__ int   g_rowstart[N_NODES];
__device__ int   g_cursor[N_NODES];
__device__ int   g_edst[N_EDGES];
__device__ int   g_bsum[256];
// W transposed + bf16 split: Wt[n][k] = W[k][n]
__device__ __nv_bfloat16 g_Wt_hi[256 * 256];
__device__ __nv_bfloat16 g_Wt_lo[256 * 256];

// ---------------------------------------------------------------------------
// helpers
// ---------------------------------------------------------------------------
__device__ __forceinline__ uint32_t smem_u32(const void* p) {
    uint32_t a;
    asm("{ .reg .u64 t; cvta.to.shared.u64 t, %1; cvt.u32.u64 %0, t; }"
        : "=r"(a) : "l"(p));
    return a;
}

__device__ __forceinline__ void ldsm_x4(uint32_t* r, uint32_t addr) {
    asm volatile("ldmatrix.sync.aligned.m8n8.x4.shared.b16 {%0,%1,%2,%3}, [%4];"
                 : "=r"(r[0]), "=r"(r[1]), "=r"(r[2]), "=r"(r[3]) : "r"(addr));
}
__device__ __forceinline__ void ldsm_x2(uint32_t* r, uint32_t addr) {
    asm volatile("ldmatrix.sync.aligned.m8n8.x2.shared.b16 {%0,%1}, [%2];"
                 : "=r"(r[0]), "=r"(r[1]) : "r"(addr));
}
__device__ __forceinline__ void mma_bf16(float* c, const uint32_t* a, const uint32_t* b) {
    asm volatile(
        "mma.sync.aligned.m16n8k16.row.col.f32.bf16.bf16.f32 "
        "{%0,%1,%2,%3}, {%4,%5,%6,%7}, {%8,%9}, {%0,%1,%2,%3};"
        : "+f"(c[0]), "+f"(c[1]), "+f"(c[2]), "+f"(c[3])
        : "r"(a[0]), "r"(a[1]), "r"(a[2]), "r"(a[3]), "r"(b[0]), "r"(b[1]));
}

// ---------------------------------------------------------------------------
// Kernel 0: zero degree array
// ---------------------------------------------------------------------------
__global__ void k_zero_deg(int n) {
    int i = blockIdx.x * blockDim.x + threadIdx.x;
    if (i < n) g_deg[i] = 0;
}

// ---------------------------------------------------------------------------
// Kernel P: W [K,N] fp32 -> Wt_hi/Wt_lo [N,K] bf16 split
// ---------------------------------------------------------------------------
__global__ void k_prep_W(const float* __restrict__ W) {
    int i = blockIdx.x * 256 + threadIdx.x;     // 0..65535
    int n = i >> 8, k = i & 255;
    float w = W[k * 256 + n];
    __nv_bfloat16 hi = __float2bfloat16(w);
    __nv_bfloat16 lo = __float2bfloat16(w - __bfloat162float(hi));
    g_Wt_hi[n * 256 + k] = hi;
    g_Wt_lo[n * 256 + k] = lo;
}

// ---------------------------------------------------------------------------
// Kernel 1: HMMA GEMM  Wh = h @ W  via bf16 hi/lo split (3 products)
// (unchanged from R4: 169.9us measured)
// ---------------------------------------------------------------------------
#define B_ROW 528
#define A_ROW 80
#define SM_BH 0
#define SM_BL 67584
#define SM_A0 135168
#define A_STAGE 20480
#define SM_AL_OFF 10240
#define GSM_TOTAL 176128

__global__ __launch_bounds__(256, 1) void k_gemm_mma(const float* __restrict__ A, int M)
{
    extern __shared__ __align__(16) char sm[];
    const uint32_t sbase = smem_u32(sm);
    const int tid  = threadIdx.x;
    const int lane = tid & 31;
    const int wid  = tid >> 5;
    const int wm   = wid >> 2;          // 0..1
    const int wn   = wid & 3;           // 0..3
    const int rowBase = blockIdx.y * 128;
    const int colBase = blockIdx.x * 128;

    // ---- stage B (hi+lo, full K) into smem
    {
        const char* srcH = (const char*)(g_Wt_hi + (size_t)colBase * 256);
        const char* srcL = (const char*)(g_Wt_lo + (size_t)colBase * 256);
        for (int i = tid; i < 128 * 32; i += 256) {
            int n = i >> 5, c = i & 31;
            *(uint4*)(sm + SM_BH + n * B_ROW + c * 16) =
                *(const uint4*)(srcH + n * 512 + c * 16);
            *(uint4*)(sm + SM_BL + n * B_ROW + c * 16) =
                *(const uint4*)(srcL + n * 512 + c * 16);
        }
    }

    float acc[4][4][4];
#pragma unroll
    for (int i = 0; i < 4; i++)
#pragma unroll
        for (int j = 0; j < 4; j++)
#pragma unroll
            for (int q = 0; q < 4; q++) acc[i][j][q] = 0.0f;

    // A prefetch: thread -> (row, k-half of 16 floats)
    const int ar   = tid >> 1;
    const int ahlf = tid & 1;
    const int grow = rowBase + ar;
    const float* aptr = A + (size_t)grow * IN_F + ahlf * 16;

    float4 pf[4];
#pragma unroll
    for (int q = 0; q < 4; q++) pf[q] = make_float4(0.f, 0.f, 0.f, 0.f);
    if (grow < M) {
#pragma unroll
        for (int q = 0; q < 4; q++) pf[q] = *(const float4*)(aptr + q * 4);
    }

    // fragment address bases
    const uint32_t a_frag_off = (uint32_t)((wm * 64 + (lane & 15)) * A_ROW + (lane >> 4) * 16);
    const int bl_ = lane & 15;
    const uint32_t b_frag_off = (uint32_t)((wn * 32 + (bl_ & 7)) * B_ROW + ((bl_ >> 3) & 1) * 16);
    const uint32_t sts_off = (uint32_t)(ar * A_ROW + ahlf * 32);

    for (int c = 0; c < 8; c++) {
        const int stage = c & 1;
        // convert pf (16 f32) -> bf16 hi/lo, store to smem stage
        {
            uint32_t hv[8], lv[8];
#pragma unroll
            for (int q = 0; q < 4; q++) {
                float x[4] = { pf[q].x, pf[q].y, pf[q].z, pf[q].w };
#pragma unroll
                for (int e = 0; e < 2; e++) {
                    float f0 = x[e * 2], f1 = x[e * 2 + 1];
                    __nv_bfloat16 h0 = __float2bfloat16(f0);
                    __nv_bfloat16 h1 = __float2bfloat16(f1);
                    __nv_bfloat16 l0 = __float2bfloat16(f0 - __bfloat162float(h0));
                    __nv_bfloat16 l1 = __float2bfloat16(f1 - __bfloat162float(h1));
                    hv[q * 2 + e] = (uint32_t)__bfloat16_as_ushort(h0) |
                                    ((uint32_t)__bfloat16_as_ushort(h1) << 16);
                    lv[q * 2 + e] = (uint32_t)__bfloat16_as_ushort(l0) |
                                    ((uint32_t)__bfloat16_as_ushort(l1) << 16);
                }
            }
            char* ab = sm + SM_A0 + stage * A_STAGE + sts_off;
            *(uint4*)(ab +  0) = make_uint4(hv[0], hv[1], hv[2], hv[3]);
            *(uint4*)(ab + 16) = make_uint4(hv[4], hv[5], hv[6], hv[7]);
            *(uint4*)(ab + SM_AL_OFF +  0) = make_uint4(lv[0], lv[1], lv[2], lv[3]);
            *(uint4*)(ab + SM_AL_OFF + 16) = make_uint4(lv[4], lv[5], lv[6], lv[7]);
        }
        __syncthreads();

        // prefetch next chunk (overlaps with compute below)
        if (c < 7 && grow < M) {
#pragma unroll
            for (int q = 0; q < 4; q++)
                pf[q] = *(const float4*)(aptr + (c + 1) * 32 + q * 4);
        }

        // compute this chunk
        const uint32_t aB = sbase + SM_A0 + stage * A_STAGE + a_frag_off;
        const uint32_t bB = sbase + b_frag_off + c * 64;   // k0 bytes = c*32*2
#pragma unroll
        for (int ks = 0; ks < 2; ks++) {
            uint32_t ahf[4][4], alf[4][4];
#pragma unroll
            for (int mf = 0; mf < 4; mf++) {
                ldsm_x4(ahf[mf], aB + mf * (16 * A_ROW) + ks * 32);
                ldsm_x4(alf[mf], aB + SM_AL_OFF + mf * (16 * A_ROW) + ks * 32);
            }
            uint32_t bhf[4][2], blf[4][2];
#pragma unroll
            for (int nf = 0; nf < 4; nf++) {
                ldsm_x2(bhf[nf], bB + SM_BH + nf * (8 * B_ROW) + ks * 32);
                ldsm_x2(blf[nf], bB + SM_BL + nf * (8 * B_ROW) + ks * 32);
            }
#pragma unroll
            for (int mf = 0; mf < 4; mf++)
#pragma unroll
                for (int nf = 0; nf < 4; nf++) {
                    mma_bf16(acc[mf][nf], ahf[mf], bhf[nf]);
                    mma_bf16(acc[mf][nf], ahf[mf], blf[nf]);
                    mma_bf16(acc[mf][nf], alf[mf], bhf[nf]);
                }
        }
    }

    // epilogue
#pragma unroll
    for (int mf = 0; mf < 4; mf++) {
        int r0 = rowBase + wm * 64 + mf * 16 + (lane >> 2);
#pragma unroll
        for (int nf = 0; nf < 4; nf++) {
            int col = colBase + wn * 32 + nf * 8 + 2 * (lane & 3);
            if (r0 < M)
                *(float2*)(g_Wh + (size_t)r0 * OUT_F + col) =
                    make_float2(acc[mf][nf][0], acc[mf][nf][1]);
            if (r0 + 8 < M)
                *(float2*)(g_Wh + (size_t)(r0 + 8) * OUT_F + col) =
                    make_float2(acc[mf][nf][2], acc[mf][nf][3]);
        }
    }
}

// ---------------------------------------------------------------------------
// Kernel 2: degree histogram over src   (adj is INT32: [2, E] row-major)
// ---------------------------------------------------------------------------
__global__ void k_count(const int* __restrict__ adj, int E) {
    int e = blockIdx.x * blockDim.x + threadIdx.x;
    if (e < E) atomicAdd(&g_deg[adj[e]], 1);
}

// ---------------------------------------------------------------------------
// Kernels 3-5: exclusive scan of g_deg -> g_rowstart (and g_cursor copy)
// ---------------------------------------------------------------------------
__global__ void k_scan1(int n) {
    __shared__ int sm[SCAN_BLK];
    int i = blockIdx.x * SCAN_BLK + threadIdx.x;
    int v = (i < n) ? g_deg[i] : 0;
    sm[threadIdx.x] = v;
    __syncthreads();
    for (int off = 1; off < SCAN_BLK; off <<= 1) {
        int add = (threadIdx.x >= off) ? sm[threadIdx.x - off] : 0;
        __syncthreads();
        sm[threadIdx.x] += add;
        __syncthreads();
    }
    if (i < n) g_rowstart[i] = sm[threadIdx.x] - v;
    if (threadIdx.x == SCAN_BLK - 1) g_bsum[blockIdx.x] = sm[SCAN_BLK - 1];
}

__global__ void k_scan2(int nb) {
    __shared__ int sm[256];
    int t = threadIdx.x;
    int v = (t < nb) ? g_bsum[t] : 0;
    sm[t] = v;
    __syncthreads();
    for (int off = 1; off < 256; off <<= 1) {
        int add = (t >= off) ? sm[t - off] : 0;
        __syncthreads();
        sm[t] += add;
        __syncthreads();
    }
    if (t < nb) g_bsum[t] = sm[t] - v;
}

__global__ void k_scan3(int n) {
    int i = blockIdx.x * blockDim.x + threadIdx.x;
    if (i < n) {
        int rs = g_rowstart[i] + g_bsum[i >> 9];
        g_rowstart[i] = rs;
        g_cursor[i]   = rs;
    }
}

// ---------------------------------------------------------------------------
// Kernel 6: scatter edges into CSR (dst per slot)
// ---------------------------------------------------------------------------
__global__ void k_scatter(const int* __restrict__ adj, int E) {
    int e = blockIdx.x * blockDim.x + threadIdx.x;
    if (e < E) {
        int s = adj[e];
        int d = adj[E + e];
        int p = atomicAdd(&g_cursor[s], 1);
        g_edst[p] = d;
    }
}

// ---------------------------------------------------------------------------
// Kernel 7: warp-per-node attention + aggregation (vectorized, unrolled x2)
// ---------------------------------------------------------------------------
#define MAXD 96

__device__ __forceinline__ float warp_sum32(float v) {
    v += __shfl_xor_sync(0xffffffffu, v, 16);
    v += __shfl_xor_sync(0xffffffffu, v, 8);
    v += __shfl_xor_sync(0xffffffffu, v, 4);
    v += __shfl_xor_sync(0xffffffffu, v, 2);
    v += __shfl_xor_sync(0xffffffffu, v, 1);
    return v;
}

__device__ __forceinline__ float edge_exp(float labi, const float* __restrict__ label,
                                          int j, int lane) {
    float v = labi * __ldg(label + (size_t)j * D_LABEL + lane);
    v = warp_sum32(v);
    float e = (v >= 0.0f) ? v : ALPHA * v;
    return __expf(e);
}

__global__ __launch_bounds__(256) void k_aggregate(
    const float* __restrict__ label,   // [N, 32]
    float* __restrict__ out,           // [N, 256]
    int n)
{
    __shared__ float sE[8][MAXD];
    __shared__ int   sJ[8][MAXD];

    const int wl   = threadIdx.x >> 5;
    const int lane = threadIdx.x & 31;
    const int w    = blockIdx.x * 8 + wl;
    if (w >= n) return;

    const float labi = label[(size_t)w * D_LABEL + lane];
    const int start = g_rowstart[w];
    const int d     = g_deg[w];

    // -------- Pass 1: attention logits -> exp, denominator (2 chains in flight)
    float denom = 0.0f;
    int k = 0;
    for (; k + 1 < d; k += 2) {
        int j0 = __ldg(g_edst + start + k);
        int j1 = __ldg(g_edst + start + k + 1);
        float v0 = labi * __ldg(label + (size_t)j0 * D_LABEL + lane);
        float v1 = labi * __ldg(label + (size_t)j1 * D_LABEL + lane);
#pragma unroll
        for (int o = 16; o > 0; o >>= 1) {
            v0 += __shfl_xor_sync(0xffffffffu, v0, o);
            v1 += __shfl_xor_sync(0xffffffffu, v1, o);
        }
        float e0 = (v0 >= 0.0f) ? v0 : ALPHA * v0;
        float e1 = (v1 >= 0.0f) ? v1 : ALPHA * v1;
        float ex0 = __expf(e0);
        float ex1 = __expf(e1);
        denom += ex0 + ex1;
        if (lane == 0) {
            if (k < MAXD)     { sE[wl][k] = ex0;     sJ[wl][k] = j0; }
            if (k + 1 < MAXD) { sE[wl][k + 1] = ex1; sJ[wl][k + 1] = j1; }
        }
    }
    if (k < d) {
        int j0 = __ldg(g_edst + start + k);
        float ex0 = edge_exp(labi, label, j0, lane);
        denom += ex0;
        if (lane == 0 && k < MAXD) { sE[wl][k] = ex0; sJ[wl][k] = j0; }
    }
    const float inv = 1.0f / fmaxf(denom, EPS_RS);
    __syncwarp();

    // -------- Pass 2: float4-vectorized weighted gather (2 edges in flight)
    // lane covers cols [lane*4, lane*4+3] and [128+lane*4, 128+lane*4+3]
    float4 a0 = make_float4(0.f, 0.f, 0.f, 0.f);
    float4 a1 = make_float4(0.f, 0.f, 0.f, 0.f);

    k = 0;
    for (; k + 1 < d; k += 2) {
        float ex0, ex1; int j0, j1;
        if (k + 1 < MAXD) {
            ex0 = sE[wl][k];     j0 = sJ[wl][k];
            ex1 = sE[wl][k + 1]; j1 = sJ[wl][k + 1];
        } else {
            j0 = __ldg(g_edst + start + k);
            j1 = __ldg(g_edst + start + k + 1);
            ex0 = edge_exp(labi, label, j0, lane);
            ex1 = edge_exp(labi, label, j1, lane);
        }
        float wt0 = ex0 * inv;
        float wt1 = ex1 * inv;
        const float4* p0 = (const float4*)(g_Wh + (size_t)j0 * OUT_F) + lane;
        const float4* p1 = (const float4*)(g_Wh + (size_t)j1 * OUT_F) + lane;
        float4 w00 = __ldg(p0);
        float4 w01 = __ldg(p0 + 32);
        float4 w10 = __ldg(p1);
        float4 w11 = __ldg(p1 + 32);
        a0.x = fmaf(wt0, w00.x, a0.x); a0.y = fmaf(wt0, w00.y, a0.y);
        a0.z = fmaf(wt0, w00.z, a0.z); a0.w = fmaf(wt0, w00.w, a0.w);
        a1.x = fmaf(wt0, w01.x, a1.x); a1.y = fmaf(wt0, w01.y, a1.y);
        a1.z = fmaf(wt0, w01.z, a1.z); a1.w = fmaf(wt0, w01.w, a1.w);
        a0.x = fmaf(wt1, w10.x, a0.x); a0.y = fmaf(wt1, w10.y, a0.y);
        a0.z = fmaf(wt1, w10.z, a0.z); a0.w = fmaf(wt1, w10.w, a0.w);
        a1.x = fmaf(wt1, w11.x, a1.x); a1.y = fmaf(wt1, w11.y, a1.y);
        a1.z = fmaf(wt1, w11.z, a1.z); a1.w = fmaf(wt1, w11.w, a1.w);
    }
    if (k < d) {
        float ex0; int j0;
        if (k < MAXD) { ex0 = sE[wl][k]; j0 = sJ[wl][k]; }
        else {
            j0 = __ldg(g_edst + start + k);
            ex0 = edge_exp(labi, label, j0, lane);
        }
        float wt0 = ex0 * inv;
        const float4* p0 = (const float4*)(g_Wh + (size_t)j0 * OUT_F) + lane;
        float4 w00 = __ldg(p0);
        float4 w01 = __ldg(p0 + 32);
        a0.x = fmaf(wt0, w00.x, a0.x); a0.y = fmaf(wt0, w00.y, a0.y);
        a0.z = fmaf(wt0, w00.z, a0.z); a0.w = fmaf(wt0, w00.w, a0.w);
        a1.x = fmaf(wt0, w01.x, a1.x); a1.y = fmaf(wt0, w01.y, a1.y);
        a1.z = fmaf(wt0, w01.z, a1.z); a1.w = fmaf(wt0, w01.w, a1.w);
    }

    float4* o4 = (float4*)(out + (size_t)w * OUT_F);
    o4[lane]      = a0;
    o4[lane + 32] = a1;
}

// ---------------------------------------------------------------------------
// Launch
// ---------------------------------------------------------------------------
extern "C" void kernel_launch(void* const* d_in, const int* in_sizes, int n_in,
                              void* d_out, int out_size)
{
    const float* h     = (const float*)d_in[0];   // [N, 256] fp32
    const float* label = (const float*)d_in[1];   // [N, 32]  fp32
    const float* W     = (const float*)d_in[2];   // [256, 256] fp32
    const int*   adj   = (const int*)d_in[3];     // [2, E] int32
    float*       out   = (float*)d_out;

    const int N = in_sizes[0] / IN_F;      // 100000
    const int E = in_sizes[3] / 2;         // 1600000

    const int T = 256;
    const int gbN = (N + T - 1) / T;
    const int gbE = (E + T - 1) / T;

    static bool attr_done = false;
    if (!attr_done) {
        cudaFuncSetAttribute(k_gemm_mma, cudaFuncAttributeMaxDynamicSharedMemorySize, GSM_TOTAL);
        attr_done = true;
    }

    k_zero_deg<<<gbN, T>>>(N);
    k_prep_W<<<256, 256>>>(W);
    k_count<<<gbE, T>>>(adj, E);

    dim3 ggrid(2, (N + 127) / 128);
    k_gemm_mma<<<ggrid, 256, GSM_TOTAL>>>(h, N);

    int nb = (N + SCAN_BLK - 1) / SCAN_BLK;
    k_scan1<<<nb, SCAN_BLK>>>(N);
    k_scan2<<<1, 256>>>(nb);
    k_scan3<<<gbN, T>>>(N);
    k_scatter<<<gbE, T>>>(adj, E);

    k_aggregate<<<(N + 7) / 8, 256>>>(label, out, N);
}

// round 6
// speedup vs baseline: 1.5630x; 1.0808x over previous
#include <cuda_runtime.h>
#include <cuda_bf16.h>
#include <math.h>
#include <stdint.h>

// Problem constants (fixed by the dataset)
#define N_NODES   100000
#define N_EDGES   1600000
#define IN_F      256
#define OUT_F     256
#define D_LABEL   32
#define ALPHA     0.2f
#define EPS_RS    1e-9f

#define SCAN_BLK  512

// Scratch (device globals: allowed; no cudaMalloc anywhere)
__device__ float g_Wh[(size_t)N_NODES * OUT_F];   // ~100 MB
__device__ float g_att[N_EDGES];
__device__ int   g_deg[N_NODES];
__device__ int   g_rowstart[N_NODES];
__device__ int   g_cursor[N_NODES];
__device__ int   g_edst[N_EDGES];
__device__ int   g_bsum[256];
// W transposed + bf16 split: Wt[n][k] = W[k][n]
__device__ __nv_bfloat16 g_Wt_hi[256 * 256];
__device__ __nv_bfloat16 g_Wt_lo[256 * 256];

// ---------------------------------------------------------------------------
// helpers
// ---------------------------------------------------------------------------
__device__ __forceinline__ uint32_t smem_u32(const void* p) {
    uint32_t a;
    asm("{ .reg .u64 t; cvta.to.shared.u64 t, %1; cvt.u32.u64 %0, t; }"
        : "=r"(a) : "l"(p));
    return a;
}

__device__ __forceinline__ void ldsm_x4(uint32_t* r, uint32_t addr) {
    asm volatile("ldmatrix.sync.aligned.m8n8.x4.shared.b16 {%0,%1,%2,%3}, [%4];"
                 : "=r"(r[0]), "=r"(r[1]), "=r"(r[2]), "=r"(r[3]) : "r"(addr));
}
__device__ __forceinline__ void ldsm_x2(uint32_t* r, uint32_t addr) {
    asm volatile("ldmatrix.sync.aligned.m8n8.x2.shared.b16 {%0,%1}, [%2];"
                 : "=r"(r[0]), "=r"(r[1]) : "r"(addr));
}
__device__ __forceinline__ void mma_bf16(float* c, const uint32_t* a, const uint32_t* b) {
    asm volatile(
        "mma.sync.aligned.m16n8k16.row.col.f32.bf16.bf16.f32 "
        "{%0,%1,%2,%3}, {%4,%5,%6,%7}, {%8,%9}, {%0,%1,%2,%3};"
        : "+f"(c[0]), "+f"(c[1]), "+f"(c[2]), "+f"(c[3])
        : "r"(a[0]), "r"(a[1]), "r"(a[2]), "r"(a[3]), "r"(b[0]), "r"(b[1]));
}

// ---------------------------------------------------------------------------
// Kernel 0: zero degree array
// ---------------------------------------------------------------------------
__global__ void k_zero_deg(int n) {
    int i = blockIdx.x * blockDim.x + threadIdx.x;
    if (i < n) g_deg[i] = 0;
}

// ---------------------------------------------------------------------------
// Kernel P: W [K,N] fp32 -> Wt_hi/Wt_lo [N,K] bf16 split
// ---------------------------------------------------------------------------
__global__ void k_prep_W(const float* __restrict__ W) {
    int i = blockIdx.x * 256 + threadIdx.x;     // 0..65535
    int n = i >> 8, k = i & 255;
    float w = W[k * 256 + n];
    __nv_bfloat16 hi = __float2bfloat16(w);
    __nv_bfloat16 lo = __float2bfloat16(w - __bfloat162float(hi));
    g_Wt_hi[n * 256 + k] = hi;
    g_Wt_lo[n * 256 + k] = lo;
}

// ---------------------------------------------------------------------------
// Kernel 1: HMMA GEMM  Wh = h @ W  via bf16 hi/lo split (3 products)
// (unchanged from R4/R5: 168.5us measured)
// ---------------------------------------------------------------------------
#define B_ROW 528
#define A_ROW 80
#define SM_BH 0
#define SM_BL 67584
#define SM_A0 135168
#define A_STAGE 20480
#define SM_AL_OFF 10240
#define GSM_TOTAL 176128

__global__ __launch_bounds__(256, 1) void k_gemm_mma(const float* __restrict__ A, int M)
{
    extern __shared__ __align__(16) char sm[];
    const uint32_t sbase = smem_u32(sm);
    const int tid  = threadIdx.x;
    const int lane = tid & 31;
    const int wid  = tid >> 5;
    const int wm   = wid >> 2;          // 0..1
    const int wn   = wid & 3;           // 0..3
    const int rowBase = blockIdx.y * 128;
    const int colBase = blockIdx.x * 128;

    // ---- stage B (hi+lo, full K) into smem
    {
        const char* srcH = (const char*)(g_Wt_hi + (size_t)colBase * 256);
        const char* srcL = (const char*)(g_Wt_lo + (size_t)colBase * 256);
        for (int i = tid; i < 128 * 32; i += 256) {
            int n = i >> 5, c = i & 31;
            *(uint4*)(sm + SM_BH + n * B_ROW + c * 16) =
                *(const uint4*)(srcH + n * 512 + c * 16);
            *(uint4*)(sm + SM_BL + n * B_ROW + c * 16) =
                *(const uint4*)(srcL + n * 512 + c * 16);
        }
    }

    float acc[4][4][4];
#pragma unroll
    for (int i = 0; i < 4; i++)
#pragma unroll
        for (int j = 0; j < 4; j++)
#pragma unroll
            for (int q = 0; q < 4; q++) acc[i][j][q] = 0.0f;

    const int ar   = tid >> 1;
    const int ahlf = tid & 1;
    const int grow = rowBase + ar;
    const float* aptr = A + (size_t)grow * IN_F + ahlf * 16;

    float4 pf[4];
#pragma unroll
    for (int q = 0; q < 4; q++) pf[q] = make_float4(0.f, 0.f, 0.f, 0.f);
    if (grow < M) {
#pragma unroll
        for (int q = 0; q < 4; q++) pf[q] = *(const float4*)(aptr + q * 4);
    }

    const uint32_t a_frag_off = (uint32_t)((wm * 64 + (lane & 15)) * A_ROW + (lane >> 4) * 16);
    const int bl_ = lane & 15;
    const uint32_t b_frag_off = (uint32_t)((wn * 32 + (bl_ & 7)) * B_ROW + ((bl_ >> 3) & 1) * 16);
    const uint32_t sts_off = (uint32_t)(ar * A_ROW + ahlf * 32);

    for (int c = 0; c < 8; c++) {
        const int stage = c & 1;
        {
            uint32_t hv[8], lv[8];
#pragma unroll
            for (int q = 0; q < 4; q++) {
                float x[4] = { pf[q].x, pf[q].y, pf[q].z, pf[q].w };
#pragma unroll
                for (int e = 0; e < 2; e++) {
                    float f0 = x[e * 2], f1 = x[e * 2 + 1];
                    __nv_bfloat16 h0 = __float2bfloat16(f0);
                    __nv_bfloat16 h1 = __float2bfloat16(f1);
                    __nv_bfloat16 l0 = __float2bfloat16(f0 - __bfloat162float(h0));
                    __nv_bfloat16 l1 = __float2bfloat16(f1 - __bfloat162float(h1));
                    hv[q * 2 + e] = (uint32_t)__bfloat16_as_ushort(h0) |
                                    ((uint32_t)__bfloat16_as_ushort(h1) << 16);
                    lv[q * 2 + e] = (uint32_t)__bfloat16_as_ushort(l0) |
                                    ((uint32_t)__bfloat16_as_ushort(l1) << 16);
                }
            }
            char* ab = sm + SM_A0 + stage * A_STAGE + sts_off;
            *(uint4*)(ab +  0) = make_uint4(hv[0], hv[1], hv[2], hv[3]);
            *(uint4*)(ab + 16) = make_uint4(hv[4], hv[5], hv[6], hv[7]);
            *(uint4*)(ab + SM_AL_OFF +  0) = make_uint4(lv[0], lv[1], lv[2], lv[3]);
            *(uint4*)(ab + SM_AL_OFF + 16) = make_uint4(lv[4], lv[5], lv[6], lv[7]);
        }
        __syncthreads();

        if (c < 7 && grow < M) {
#pragma unroll
            for (int q = 0; q < 4; q++)
                pf[q] = *(const float4*)(aptr + (c + 1) * 32 + q * 4);
        }

        const uint32_t aB = sbase + SM_A0 + stage * A_STAGE + a_frag_off;
        const uint32_t bB = sbase + b_frag_off + c * 64;
#pragma unroll
        for (int ks = 0; ks < 2; ks++) {
            uint32_t ahf[4][4], alf[4][4];
#pragma unroll
            for (int mf = 0; mf < 4; mf++) {
                ldsm_x4(ahf[mf], aB + mf * (16 * A_ROW) + ks * 32);
                ldsm_x4(alf[mf], aB + SM_AL_OFF + mf * (16 * A_ROW) + ks * 32);
            }
            uint32_t bhf[4][2], blf[4][2];
#pragma unroll
            for (int nf = 0; nf < 4; nf++) {
                ldsm_x2(bhf[nf], bB + SM_BH + nf * (8 * B_ROW) + ks * 32);
                ldsm_x2(blf[nf], bB + SM_BL + nf * (8 * B_ROW) + ks * 32);
            }
#pragma unroll
            for (int mf = 0; mf < 4; mf++)
#pragma unroll
                for (int nf = 0; nf < 4; nf++) {
                    mma_bf16(acc[mf][nf], ahf[mf], bhf[nf]);
                    mma_bf16(acc[mf][nf], ahf[mf], blf[nf]);
                    mma_bf16(acc[mf][nf], alf[mf], bhf[nf]);
                }
        }
    }

#pragma unroll
    for (int mf = 0; mf < 4; mf++) {
        int r0 = rowBase + wm * 64 + mf * 16 + (lane >> 2);
#pragma unroll
        for (int nf = 0; nf < 4; nf++) {
            int col = colBase + wn * 32 + nf * 8 + 2 * (lane & 3);
            if (r0 < M)
                *(float2*)(g_Wh + (size_t)r0 * OUT_F + col) =
                    make_float2(acc[mf][nf][0], acc[mf][nf][1]);
            if (r0 + 8 < M)
                *(float2*)(g_Wh + (size_t)(r0 + 8) * OUT_F + col) =
                    make_float2(acc[mf][nf][2], acc[mf][nf][3]);
        }
    }
}

// ---------------------------------------------------------------------------
// Kernel 2: degree histogram over src   (adj is INT32: [2, E] row-major)
// ---------------------------------------------------------------------------
__global__ void k_count(const int* __restrict__ adj, int E) {
    int e = blockIdx.x * blockDim.x + threadIdx.x;
    if (e < E) atomicAdd(&g_deg[adj[e]], 1);
}

// ---------------------------------------------------------------------------
// Kernels 3-5: exclusive scan of g_deg -> g_rowstart (and g_cursor copy)
// ---------------------------------------------------------------------------
__global__ void k_scan1(int n) {
    __shared__ int sm[SCAN_BLK];
    int i = blockIdx.x * SCAN_BLK + threadIdx.x;
    int v = (i < n) ? g_deg[i] : 0;
    sm[threadIdx.x] = v;
    __syncthreads();
    for (int off = 1; off < SCAN_BLK; off <<= 1) {
        int add = (threadIdx.x >= off) ? sm[threadIdx.x - off] : 0;
        __syncthreads();
        sm[threadIdx.x] += add;
        __syncthreads();
    }
    if (i < n) g_rowstart[i] = sm[threadIdx.x] - v;
    if (threadIdx.x == SCAN_BLK - 1) g_bsum[blockIdx.x] = sm[SCAN_BLK - 1];
}

__global__ void k_scan2(int nb) {
    __shared__ int sm[256];
    int t = threadIdx.x;
    int v = (t < nb) ? g_bsum[t] : 0;
    sm[t] = v;
    __syncthreads();
    for (int off = 1; off < 256; off <<= 1) {
        int add = (t >= off) ? sm[t - off] : 0;
        __syncthreads();
        sm[t] += add;
        __syncthreads();
    }
    if (t < nb) g_bsum[t] = sm[t] - v;
}

__global__ void k_scan3(int n) {
    int i = blockIdx.x * blockDim.x + threadIdx.x;
    if (i < n) {
        int rs = g_rowstart[i] + g_bsum[i >> 9];
        g_rowstart[i] = rs;
        g_cursor[i]   = rs;
    }
}

// ---------------------------------------------------------------------------
// Kernel 6: scatter edges into CSR (dst per slot)
// ---------------------------------------------------------------------------
__global__ void k_scatter(const int* __restrict__ adj, int E) {
    int e = blockIdx.x * blockDim.x + threadIdx.x;
    if (e < E) {
        int s = adj[e];
        int d = adj[E + e];
        int p = atomicAdd(&g_cursor[s], 1);
        g_edst[p] = d;
    }
}

// ---------------------------------------------------------------------------
// Kernel 7a: warp-per-node attention -> normalized weights in g_att
// lane (k mod 32) writes edge k's exp; same lane rescales it (no fence needed)
// ---------------------------------------------------------------------------
__global__ __launch_bounds__(256) void k_attention(
    const float* __restrict__ label,   // [N, 32]
    int n)
{
    const int wl   = threadIdx.x >> 5;
    const int lane = threadIdx.x & 31;
    const int w    = blockIdx.x * 8 + wl;
    if (w >= n) return;

    const float labi = label[(size_t)w * D_LABEL + lane];
    const int start = g_rowstart[w];
    const int d     = g_deg[w];

    float denom = 0.0f;
    int k = 0;
    for (; k + 1 < d; k += 2) {
        int j0 = __ldg(g_edst + start + k);
        int j1 = __ldg(g_edst + start + k + 1);
        float v0 = labi * __ldg(label + (size_t)j0 * D_LABEL + lane);
        float v1 = labi * __ldg(label + (size_t)j1 * D_LABEL + lane);
#pragma unroll
        for (int o = 16; o > 0; o >>= 1) {
            v0 += __shfl_xor_sync(0xffffffffu, v0, o);
            v1 += __shfl_xor_sync(0xffffffffu, v1, o);
        }
        float e0 = (v0 >= 0.0f) ? v0 : ALPHA * v0;
        float e1 = (v1 >= 0.0f) ? v1 : ALPHA * v1;
        float ex0 = __expf(e0);
        float ex1 = __expf(e1);
        denom += ex0 + ex1;
        if (lane == (k & 31))       g_att[start + k]     = ex0;
        if (lane == ((k + 1) & 31)) g_att[start + k + 1] = ex1;
    }
    if (k < d) {
        int j0 = __ldg(g_edst + start + k);
        float v0 = labi * __ldg(label + (size_t)j0 * D_LABEL + lane);
#pragma unroll
        for (int o = 16; o > 0; o >>= 1)
            v0 += __shfl_xor_sync(0xffffffffu, v0, o);
        float e0 = (v0 >= 0.0f) ? v0 : ALPHA * v0;
        float ex0 = __expf(e0);
        denom += ex0;
        if (lane == (k & 31)) g_att[start + k] = ex0;
    }
    const float inv = 1.0f / fmaxf(denom, EPS_RS);
    // each lane rescales exactly the slots it wrote (t ≡ lane mod 32)
    for (int t = lane; t < d; t += 32)
        g_att[start + t] *= inv;
}

// ---------------------------------------------------------------------------
// Kernel 7b: gather — 2 warps per node (column halves), 4 edges in flight
// ---------------------------------------------------------------------------
__global__ __launch_bounds__(256) void k_gather(
    float* __restrict__ out,   // [N, 256]
    int n)
{
    const int gw   = blockIdx.x * 8 + (threadIdx.x >> 5);
    const int w    = gw >> 1;
    const int half = gw & 1;
    const int lane = threadIdx.x & 31;
    if (w >= n) return;

    const int start = g_rowstart[w];
    const int d     = g_deg[w];
    const float* base = g_Wh + half * 128 + lane * 4;

    float4 acc = make_float4(0.f, 0.f, 0.f, 0.f);
    int k = 0;
    for (; k + 3 < d; k += 4) {
        int j0 = __ldg(g_edst + start + k);
        int j1 = __ldg(g_edst + start + k + 1);
        int j2 = __ldg(g_edst + start + k + 2);
        int j3 = __ldg(g_edst + start + k + 3);
        float a0 = __ldg(g_att + start + k);
        float a1 = __ldg(g_att + start + k + 1);
        float a2 = __ldg(g_att + start + k + 2);
        float a3 = __ldg(g_att + start + k + 3);
        float4 w0 = __ldg((const float4*)(base + (size_t)j0 * OUT_F));
        float4 w1 = __ldg((const float4*)(base + (size_t)j1 * OUT_F));
        float4 w2 = __ldg((const float4*)(base + (size_t)j2 * OUT_F));
        float4 w3 = __ldg((const float4*)(base + (size_t)j3 * OUT_F));
        acc.x = fmaf(a0, w0.x, acc.x); acc.y = fmaf(a0, w0.y, acc.y);
        acc.z = fmaf(a0, w0.z, acc.z); acc.w = fmaf(a0, w0.w, acc.w);
        acc.x = fmaf(a1, w1.x, acc.x); acc.y = fmaf(a1, w1.y, acc.y);
        acc.z = fmaf(a1, w1.z, acc.z); acc.w = fmaf(a1, w1.w, acc.w);
        acc.x = fmaf(a2, w2.x, acc.x); acc.y = fmaf(a2, w2.y, acc.y);
        acc.z = fmaf(a2, w2.z, acc.z); acc.w = fmaf(a2, w2.w, acc.w);
        acc.x = fmaf(a3, w3.x, acc.x); acc.y = fmaf(a3, w3.y, acc.y);
        acc.z = fmaf(a3, w3.z, acc.z); acc.w = fmaf(a3, w3.w, acc.w);
    }
    for (; k < d; k++) {
        int j0 = __ldg(g_edst + start + k);
        float a0 = __ldg(g_att + start + k);
        float4 w0 = __ldg((const float4*)(base + (size_t)j0 * OUT_F));
        acc.x = fmaf(a0, w0.x, acc.x); acc.y = fmaf(a0, w0.y, acc.y);
        acc.z = fmaf(a0, w0.z, acc.z); acc.w = fmaf(a0, w0.w, acc.w);
    }

    *(float4*)(out + (size_t)w * OUT_F + half * 128 + lane * 4) = acc;
}

// ---------------------------------------------------------------------------
// Launch — stream fork: branch A = prep_W + GEMM (default stream),
//                        branch B = CSR build + attention (s2), join -> gather
// ---------------------------------------------------------------------------
extern "C" void kernel_launch(void* const* d_in, const int* in_sizes, int n_in,
                              void* d_out, int out_size)
{
    const float* h     = (const float*)d_in[0];   // [N, 256] fp32
    const float* label = (const float*)d_in[1];   // [N, 32]  fp32
    const float* W     = (const float*)d_in[2];   // [256, 256] fp32
    const int*   adj   = (const int*)d_in[3];     // [2, E] int32
    float*       out   = (float*)d_out;

    const int N = in_sizes[0] / IN_F;      // 100000
    const int E = in_sizes[3] / 2;         // 1600000

    const int T = 256;
    const int gbN = (N + T - 1) / T;
    const int gbE = (E + T - 1) / T;

    static cudaStream_t s2 = nullptr;
    static cudaEvent_t  evF = nullptr, evJ = nullptr;
    if (s2 == nullptr) {
        cudaFuncSetAttribute(k_gemm_mma, cudaFuncAttributeMaxDynamicSharedMemorySize, GSM_TOTAL);
        cudaStreamCreateWithFlags(&s2, cudaStreamNonBlocking);
        cudaEventCreateWithFlags(&evF, cudaEventDisableTiming);
        cudaEventCreateWithFlags(&evJ, cudaEventDisableTiming);
    }

    // fork
    cudaEventRecord(evF, 0);
    cudaStreamWaitEvent(s2, evF, 0);

    // ---- branch B (s2): CSR build + attention weights
    k_zero_deg<<<gbN, T, 0, s2>>>(N);
    k_count<<<gbE, T, 0, s2>>>(adj, E);
    int nb = (N + SCAN_BLK - 1) / SCAN_BLK;
    k_scan1<<<nb, SCAN_BLK, 0, s2>>>(N);
    k_scan2<<<1, 256, 0, s2>>>(nb);
    k_scan3<<<gbN, T, 0, s2>>>(N);
    k_scatter<<<gbE, T, 0, s2>>>(adj, E);
    k_attention<<<(N + 7) / 8, 256, 0, s2>>>(label, N);
    cudaEventRecord(evJ, s2);

    // ---- branch A (default stream): GEMM
    k_prep_W<<<256, 256>>>(W);
    dim3 ggrid(2, (N + 127) / 128);
    k_gemm_mma<<<ggrid, 256, GSM_TOTAL>>>(h, N);

    // join, then gather
    cudaStreamWaitEvent(0, evJ, 0);
    k_gather<<<(2 * N + 7) / 8, 256>>>(out, N);
}

// round 7
// speedup vs baseline: 1.9030x; 1.2175x over previous
#include <cuda_runtime.h>
#include <cuda_bf16.h>
#include <cuda_fp16.h>
#include <math.h>
#include <stdint.h>

// Problem constants (fixed by the dataset)
#define N_NODES   100000
#define N_EDGES   1600000
#define IN_F      256
#define OUT_F     256
#define D_LABEL   32
#define ALPHA     0.2f
#define EPS_RS    1e-9f

#define SCAN_BLK  512

// Scratch (device globals: allowed; no cudaMalloc anywhere)
__device__ __half g_Wh_h[(size_t)N_NODES * OUT_F];   // ~50 MB (fp16 Wh)
__device__ float g_att[N_EDGES];
__device__ int   g_deg[N_NODES];
__device__ int   g_rowstart[N_NODES];
__device__ int   g_cursor[N_NODES];
__device__ int   g_edst[N_EDGES];
__device__ int   g_bsum[256];
// W transposed + bf16 split: Wt[n][k] = W[k][n]
__device__ __nv_bfloat16 g_Wt_hi[256 * 256];
__device__ __nv_bfloat16 g_Wt_lo[256 * 256];

// ---------------------------------------------------------------------------
// helpers
// ---------------------------------------------------------------------------
__device__ __forceinline__ uint32_t smem_u32(const void* p) {
    uint32_t a;
    asm("{ .reg .u64 t; cvta.to.shared.u64 t, %1; cvt.u32.u64 %0, t; }"
        : "=r"(a) : "l"(p));
    return a;
}

__device__ __forceinline__ void ldsm_x4(uint32_t* r, uint32_t addr) {
    asm volatile("ldmatrix.sync.aligned.m8n8.x4.shared.b16 {%0,%1,%2,%3}, [%4];"
                 : "=r"(r[0]), "=r"(r[1]), "=r"(r[2]), "=r"(r[3]) : "r"(addr));
}
__device__ __forceinline__ void ldsm_x2(uint32_t* r, uint32_t addr) {
    asm volatile("ldmatrix.sync.aligned.m8n8.x2.shared.b16 {%0,%1}, [%2];"
                 : "=r"(r[0]), "=r"(r[1]) : "r"(addr));
}
__device__ __forceinline__ void mma_bf16(float* c, const uint32_t* a, const uint32_t* b) {
    asm volatile(
        "mma.sync.aligned.m16n8k16.row.col.f32.bf16.bf16.f32 "
        "{%0,%1,%2,%3}, {%4,%5,%6,%7}, {%8,%9}, {%0,%1,%2,%3};"
        : "+f"(c[0]), "+f"(c[1]), "+f"(c[2]), "+f"(c[3])
        : "r"(a[0]), "r"(a[1]), "r"(a[2]), "r"(a[3]), "r"(b[0]), "r"(b[1]));
}

// ---------------------------------------------------------------------------
// Kernel 0: zero degree array
// ---------------------------------------------------------------------------
__global__ void k_zero_deg(int n) {
    int i = blockIdx.x * blockDim.x + threadIdx.x;
    if (i < n) g_deg[i] = 0;
}

// ---------------------------------------------------------------------------
// Kernel P: W [K,N] fp32 -> Wt_hi/Wt_lo [N,K] bf16 split
// ---------------------------------------------------------------------------
__global__ void k_prep_W(const float* __restrict__ W) {
    int i = blockIdx.x * 256 + threadIdx.x;     // 0..65535
    int n = i >> 8, k = i & 255;
    float w = W[k * 256 + n];
    __nv_bfloat16 hi = __float2bfloat16(w);
    __nv_bfloat16 lo = __float2bfloat16(w - __bfloat162float(hi));
    g_Wt_hi[n * 256 + k] = hi;
    g_Wt_lo[n * 256 + k] = lo;
}

// ---------------------------------------------------------------------------
// Kernel 1: HMMA GEMM  Wh = h @ W  via bf16 hi/lo split (3 products)
// mainloop unchanged; epilogue now stores fp16 (half2)
// ---------------------------------------------------------------------------
#define B_ROW 528
#define A_ROW 80
#define SM_BH 0
#define SM_BL 67584
#define SM_A0 135168
#define A_STAGE 20480
#define SM_AL_OFF 10240
#define GSM_TOTAL 176128

__global__ __launch_bounds__(256, 1) void k_gemm_mma(const float* __restrict__ A, int M)
{
    extern __shared__ __align__(16) char sm[];
    const uint32_t sbase = smem_u32(sm);
    const int tid  = threadIdx.x;
    const int lane = tid & 31;
    const int wid  = tid >> 5;
    const int wm   = wid >> 2;          // 0..1
    const int wn   = wid & 3;           // 0..3
    const int rowBase = blockIdx.y * 128;
    const int colBase = blockIdx.x * 128;

    // ---- stage B (hi+lo, full K) into smem
    {
        const char* srcH = (const char*)(g_Wt_hi + (size_t)colBase * 256);
        const char* srcL = (const char*)(g_Wt_lo + (size_t)colBase * 256);
        for (int i = tid; i < 128 * 32; i += 256) {
            int n = i >> 5, c = i & 31;
            *(uint4*)(sm + SM_BH + n * B_ROW + c * 16) =
                *(const uint4*)(srcH + n * 512 + c * 16);
            *(uint4*)(sm + SM_BL + n * B_ROW + c * 16) =
                *(const uint4*)(srcL + n * 512 + c * 16);
        }
    }

    float acc[4][4][4];
#pragma unroll
    for (int i = 0; i < 4; i++)
#pragma unroll
        for (int j = 0; j < 4; j++)
#pragma unroll
            for (int q = 0; q < 4; q++) acc[i][j][q] = 0.0f;

    const int ar   = tid >> 1;
    const int ahlf = tid & 1;
    const int grow = rowBase + ar;
    const float* aptr = A + (size_t)grow * IN_F + ahlf * 16;

    float4 pf[4];
#pragma unroll
    for (int q = 0; q < 4; q++) pf[q] = make_float4(0.f, 0.f, 0.f, 0.f);
    if (grow < M) {
#pragma unroll
        for (int q = 0; q < 4; q++) pf[q] = *(const float4*)(aptr + q * 4);
    }

    const uint32_t a_frag_off = (uint32_t)((wm * 64 + (lane & 15)) * A_ROW + (lane >> 4) * 16);
    const int bl_ = lane & 15;
    const uint32_t b_frag_off = (uint32_t)((wn * 32 + (bl_ & 7)) * B_ROW + ((bl_ >> 3) & 1) * 16);
    const uint32_t sts_off = (uint32_t)(ar * A_ROW + ahlf * 32);

    for (int c = 0; c < 8; c++) {
        const int stage = c & 1;
        {
            uint32_t hv[8], lv[8];
#pragma unroll
            for (int q = 0; q < 4; q++) {
                float x[4] = { pf[q].x, pf[q].y, pf[q].z, pf[q].w };
#pragma unroll
                for (int e = 0; e < 2; e++) {
                    float f0 = x[e * 2], f1 = x[e * 2 + 1];
                    __nv_bfloat16 h0 = __float2bfloat16(f0);
                    __nv_bfloat16 h1 = __float2bfloat16(f1);
                    __nv_bfloat16 l0 = __float2bfloat16(f0 - __bfloat162float(h0));
                    __nv_bfloat16 l1 = __float2bfloat16(f1 - __bfloat162float(h1));
                    hv[q * 2 + e] = (uint32_t)__bfloat16_as_ushort(h0) |
                                    ((uint32_t)__bfloat16_as_ushort(h1) << 16);
                    lv[q * 2 + e] = (uint32_t)__bfloat16_as_ushort(l0) |
                                    ((uint32_t)__bfloat16_as_ushort(l1) << 16);
                }
            }
            char* ab = sm + SM_A0 + stage * A_STAGE + sts_off;
            *(uint4*)(ab +  0) = make_uint4(hv[0], hv[1], hv[2], hv[3]);
            *(uint4*)(ab + 16) = make_uint4(hv[4], hv[5], hv[6], hv[7]);
            *(uint4*)(ab + SM_AL_OFF +  0) = make_uint4(lv[0], lv[1], lv[2], lv[3]);
            *(uint4*)(ab + SM_AL_OFF + 16) = make_uint4(lv[4], lv[5], lv[6], lv[7]);
        }
        __syncthreads();

        if (c < 7 && grow < M) {
#pragma unroll
            for (int q = 0; q < 4; q++)
                pf[q] = *(const float4*)(aptr + (c + 1) * 32 + q * 4);
        }

        const uint32_t aB = sbase + SM_A0 + stage * A_STAGE + a_frag_off;
        const uint32_t bB = sbase + b_frag_off + c * 64;
#pragma unroll
        for (int ks = 0; ks < 2; ks++) {
            uint32_t ahf[4][4], alf[4][4];
#pragma unroll
            for (int mf = 0; mf < 4; mf++) {
                ldsm_x4(ahf[mf], aB + mf * (16 * A_ROW) + ks * 32);
                ldsm_x4(alf[mf], aB + SM_AL_OFF + mf * (16 * A_ROW) + ks * 32);
            }
            uint32_t bhf[4][2], blf[4][2];
#pragma unroll
            for (int nf = 0; nf < 4; nf++) {
                ldsm_x2(bhf[nf], bB + SM_BH + nf * (8 * B_ROW) + ks * 32);
                ldsm_x2(blf[nf], bB + SM_BL + nf * (8 * B_ROW) + ks * 32);
            }
#pragma unroll
            for (int mf = 0; mf < 4; mf++)
#pragma unroll
                for (int nf = 0; nf < 4; nf++) {
                    mma_bf16(acc[mf][nf], ahf[mf], bhf[nf]);
                    mma_bf16(acc[mf][nf], ahf[mf], blf[nf]);
                    mma_bf16(acc[mf][nf], alf[mf], bhf[nf]);
                }
        }
    }

    // epilogue -> fp16
#pragma unroll
    for (int mf = 0; mf < 4; mf++) {
        int r0 = rowBase + wm * 64 + mf * 16 + (lane >> 2);
#pragma unroll
        for (int nf = 0; nf < 4; nf++) {
            int col = colBase + wn * 32 + nf * 8 + 2 * (lane & 3);
            if (r0 < M)
                *(__half2*)(g_Wh_h + (size_t)r0 * OUT_F + col) =
                    __floats2half2_rn(acc[mf][nf][0], acc[mf][nf][1]);
            if (r0 + 8 < M)
                *(__half2*)(g_Wh_h + (size_t)(r0 + 8) * OUT_F + col) =
                    __floats2half2_rn(acc[mf][nf][2], acc[mf][nf][3]);
        }
    }
}

// ---------------------------------------------------------------------------
// Kernel 2: degree histogram over src   (adj is INT32: [2, E] row-major)
// ---------------------------------------------------------------------------
__global__ void k_count(const int* __restrict__ adj, int E) {
    int e = blockIdx.x * blockDim.x + threadIdx.x;
    if (e < E) atomicAdd(&g_deg[adj[e]], 1);
}

// ---------------------------------------------------------------------------
// Kernels 3-5: exclusive scan of g_deg -> g_rowstart (and g_cursor copy)
// ---------------------------------------------------------------------------
__global__ void k_scan1(int n) {
    __shared__ int sm[SCAN_BLK];
    int i = blockIdx.x * SCAN_BLK + threadIdx.x;
    int v = (i < n) ? g_deg[i] : 0;
    sm[threadIdx.x] = v;
    __syncthreads();
    for (int off = 1; off < SCAN_BLK; off <<= 1) {
        int add = (threadIdx.x >= off) ? sm[threadIdx.x - off] : 0;
        __syncthreads();
        sm[threadIdx.x] += add;
        __syncthreads();
    }
    if (i < n) g_rowstart[i] = sm[threadIdx.x] - v;
    if (threadIdx.x == SCAN_BLK - 1) g_bsum[blockIdx.x] = sm[SCAN_BLK - 1];
}

__global__ void k_scan2(int nb) {
    __shared__ int sm[256];
    int t = threadIdx.x;
    int v = (t < nb) ? g_bsum[t] : 0;
    sm[t] = v;
    __syncthreads();
    for (int off = 1; off < 256; off <<= 1) {
        int add = (t >= off) ? sm[t - off] : 0;
        __syncthreads();
        sm[t] += add;
        __syncthreads();
    }
    if (t < nb) g_bsum[t] = sm[t] - v;
}

__global__ void k_scan3(int n) {
    int i = blockIdx.x * blockDim.x + threadIdx.x;
    if (i < n) {
        int rs = g_rowstart[i] + g_bsum[i >> 9];
        g_rowstart[i] = rs;
        g_cursor[i]   = rs;
    }
}

// ---------------------------------------------------------------------------
// Kernel 6: scatter edges into CSR (dst per slot)
// ---------------------------------------------------------------------------
__global__ void k_scatter(const int* __restrict__ adj, int E) {
    int e = blockIdx.x * blockDim.x + threadIdx.x;
    if (e < E) {
        int s = adj[e];
        int d = adj[E + e];
        int p = atomicAdd(&g_cursor[s], 1);
        g_edst[p] = d;
    }
}

// ---------------------------------------------------------------------------
// Kernel 7a: warp-per-node attention -> normalized weights in g_att
// ---------------------------------------------------------------------------
__global__ __launch_bounds__(256) void k_attention(
    const float* __restrict__ label,   // [N, 32]
    int n)
{
    const int wl   = threadIdx.x >> 5;
    const int lane = threadIdx.x & 31;
    const int w    = blockIdx.x * 8 + wl;
    if (w >= n) return;

    const float labi = label[(size_t)w * D_LABEL + lane];
    const int start = g_rowstart[w];
    const int d     = g_deg[w];

    float denom = 0.0f;
    int k = 0;
    for (; k + 1 < d; k += 2) {
        int j0 = __ldg(g_edst + start + k);
        int j1 = __ldg(g_edst + start + k + 1);
        float v0 = labi * __ldg(label + (size_t)j0 * D_LABEL + lane);
        float v1 = labi * __ldg(label + (size_t)j1 * D_LABEL + lane);
#pragma unroll
        for (int o = 16; o > 0; o >>= 1) {
            v0 += __shfl_xor_sync(0xffffffffu, v0, o);
            v1 += __shfl_xor_sync(0xffffffffu, v1, o);
        }
        float e0 = (v0 >= 0.0f) ? v0 : ALPHA * v0;
        float e1 = (v1 >= 0.0f) ? v1 : ALPHA * v1;
        float ex0 = __expf(e0);
        float ex1 = __expf(e1);
        denom += ex0 + ex1;
        if (lane == (k & 31))       g_att[start + k]     = ex0;
        if (lane == ((k + 1) & 31)) g_att[start + k + 1] = ex1;
    }
    if (k < d) {
        int j0 = __ldg(g_edst + start + k);
        float v0 = labi * __ldg(label + (size_t)j0 * D_LABEL + lane);
#pragma unroll
        for (int o = 16; o > 0; o >>= 1)
            v0 += __shfl_xor_sync(0xffffffffu, v0, o);
        float e0 = (v0 >= 0.0f) ? v0 : ALPHA * v0;
        float ex0 = __expf(e0);
        denom += ex0;
        if (lane == (k & 31)) g_att[start + k] = ex0;
    }
    const float inv = 1.0f / fmaxf(denom, EPS_RS);
    for (int t = lane; t < d; t += 32)
        g_att[start + t] *= inv;
}

// ---------------------------------------------------------------------------
// Kernel 7b: gather — 1 warp per node; lane covers 8 cols (uint4 of fp16);
// 4 edges in flight
// ---------------------------------------------------------------------------
__device__ __forceinline__ void fma8_h(float* acc, uint4 v, float a) {
    float2 f;
    f = __half22float2(*(__half2*)&v.x);
    acc[0] = fmaf(a, f.x, acc[0]); acc[1] = fmaf(a, f.y, acc[1]);
    f = __half22float2(*((__half2*)&v.x + 1));
    acc[2] = fmaf(a, f.x, acc[2]); acc[3] = fmaf(a, f.y, acc[3]);
    f = __half22float2(*(__half2*)&v.z);
    acc[4] = fmaf(a, f.x, acc[4]); acc[5] = fmaf(a, f.y, acc[5]);
    f = __half22float2(*((__half2*)&v.z + 1));
    acc[6] = fmaf(a, f.x, acc[6]); acc[7] = fmaf(a, f.y, acc[7]);
}

__global__ __launch_bounds__(256) void k_gather(
    float* __restrict__ out,   // [N, 256]
    int n)
{
    const int w    = blockIdx.x * 8 + (threadIdx.x >> 5);
    const int lane = threadIdx.x & 31;
    if (w >= n) return;

    const int start = g_rowstart[w];
    const int d     = g_deg[w];
    const __half* base = g_Wh_h + lane * 8;   // 16B per lane, 512B per warp row

    float acc[8];
#pragma unroll
    for (int q = 0; q < 8; q++) acc[q] = 0.0f;

    int k = 0;
    for (; k + 3 < d; k += 4) {
        int j0 = __ldg(g_edst + start + k);
        int j1 = __ldg(g_edst + start + k + 1);
        int j2 = __ldg(g_edst + start + k + 2);
        int j3 = __ldg(g_edst + start + k + 3);
        float a0 = __ldg(g_att + start + k);
        float a1 = __ldg(g_att + start + k + 1);
        float a2 = __ldg(g_att + start + k + 2);
        float a3 = __ldg(g_att + start + k + 3);
        uint4 v0 = __ldg((const uint4*)(base + (size_t)j0 * OUT_F));
        uint4 v1 = __ldg((const uint4*)(base + (size_t)j1 * OUT_F));
        uint4 v2 = __ldg((const uint4*)(base + (size_t)j2 * OUT_F));
        uint4 v3 = __ldg((const uint4*)(base + (size_t)j3 * OUT_F));
        fma8_h(acc, v0, a0);
        fma8_h(acc, v1, a1);
        fma8_h(acc, v2, a2);
        fma8_h(acc, v3, a3);
    }
    for (; k < d; k++) {
        int j0 = __ldg(g_edst + start + k);
        float a0 = __ldg(g_att + start + k);
        uint4 v0 = __ldg((const uint4*)(base + (size_t)j0 * OUT_F));
        fma8_h(acc, v0, a0);
    }

    float* o = out + (size_t)w * OUT_F + lane * 8;
    *(float4*)(o + 0) = make_float4(acc[0], acc[1], acc[2], acc[3]);
    *(float4*)(o + 4) = make_float4(acc[4], acc[5], acc[6], acc[7]);
}

// ---------------------------------------------------------------------------
// Launch — stream fork: branch A = prep_W + GEMM (default stream),
//                        branch B = CSR build + attention (s2), join -> gather
// ---------------------------------------------------------------------------
extern "C" void kernel_launch(void* const* d_in, const int* in_sizes, int n_in,
                              void* d_out, int out_size)
{
    const float* h     = (const float*)d_in[0];   // [N, 256] fp32
    const float* label = (const float*)d_in[1];   // [N, 32]  fp32
    const float* W     = (const float*)d_in[2];   // [256, 256] fp32
    const int*   adj   = (const int*)d_in[3];     // [2, E] int32
    float*       out   = (float*)d_out;

    const int N = in_sizes[0] / IN_F;      // 100000
    const int E = in_sizes[3] / 2;         // 1600000

    const int T = 256;
    const int gbN = (N + T - 1) / T;
    const int gbE = (E + T - 1) / T;

    static cudaStream_t s2 = nullptr;
    static cudaEvent_t  evF = nullptr, evJ = nullptr;
    if (s2 == nullptr) {
        cudaFuncSetAttribute(k_gemm_mma, cudaFuncAttributeMaxDynamicSharedMemorySize, GSM_TOTAL);
        cudaStreamCreateWithFlags(&s2, cudaStreamNonBlocking);
        cudaEventCreateWithFlags(&evF, cudaEventDisableTiming);
        cudaEventCreateWithFlags(&evJ, cudaEventDisableTiming);
    }

    // fork
    cudaEventRecord(evF, 0);
    cudaStreamWaitEvent(s2, evF, 0);

    // ---- branch B (s2): CSR build + attention weights
    k_zero_deg<<<gbN, T, 0, s2>>>(N);
    k_count<<<gbE, T, 0, s2>>>(adj, E);
    int nb = (N + SCAN_BLK - 1) / SCAN_BLK;
    k_scan1<<<nb, SCAN_BLK, 0, s2>>>(N);
    k_scan2<<<1, 256, 0, s2>>>(nb);
    k_scan3<<<gbN, T, 0, s2>>>(N);
    k_scatter<<<gbE, T, 0, s2>>>(adj, E);
    k_attention<<<(N + 7) / 8, 256, 0, s2>>>(label, N);
    cudaEventRecord(evJ, s2);

    // ---- branch A (default stream): GEMM
    k_prep_W<<<256, 256>>>(W);
    dim3 ggrid(2, (N + 127) / 128);
    k_gemm_mma<<<ggrid, 256, GSM_TOTAL>>>(h, N);

    // join, then gather
    cudaStreamWaitEvent(0, evJ, 0);
    k_gather<<<(N + 7) / 8, 256>>>(out, N);
}